// round 12
// baseline (speedup 1.0000x reference)
#include <cuda_runtime.h>
#include <cuda_fp16.h>
#include <cstdint>
#include <cstddef>

#define T_TOK 16384
#define D_DIM 1024
#define F_DIM 4096
#define E_EXP 8
#define ALPHA_F 2.0f

// ---- device scratch (allocation-free; all fp16 hi-only) ----
__device__ __half g_hid[(size_t)T_TOK * F_DIM];
__device__ __half g_x[(size_t)T_TOK * D_DIM];
__device__ __half g_wi[(size_t)F_DIM * D_DIM];
__device__ __half g_wo[(size_t)D_DIM * F_DIM];
__device__ __half g_U1[T_TOK * 32];
__device__ __half g_U2[T_TOK * 32];
__device__ __half g_wbc1[F_DIM * 16];
__device__ __half g_wbe1[E_EXP * F_DIM * 16];
__device__ __half g_wbc2[D_DIM * 16];
__device__ __half g_wbe2[E_EXP * D_DIM * 16];
__device__ __half g_wac1[16 * D_DIM];
__device__ __half g_wae1[E_EXP * 16 * D_DIM];
__device__ __half g_wac2[16 * F_DIM];
__device__ __half g_wae2[E_EXP * 16 * F_DIM];

// ---------------- helpers ----------------
__device__ __forceinline__ uint32_t smem_u32(const void* p) {
    uint32_t a;
    asm("{ .reg .u64 t; cvta.to.shared.u64 t, %1; cvt.u32.u64 %0, t; }" : "=r"(a) : "l"(p));
    return a;
}
__device__ __forceinline__ void ldsm_x4(uint32_t* r, uint32_t addr) {
    asm volatile("ldmatrix.sync.aligned.m8n8.x4.shared.b16 {%0,%1,%2,%3}, [%4];"
                 : "=r"(r[0]), "=r"(r[1]), "=r"(r[2]), "=r"(r[3]) : "r"(addr));
}
__device__ __forceinline__ void mma_f16(float* d, const uint32_t* a, const uint32_t* b) {
    asm volatile(
        "mma.sync.aligned.m16n8k16.row.col.f32.f16.f16.f32 "
        "{%0,%1,%2,%3},{%4,%5,%6,%7},{%8,%9},{%0,%1,%2,%3};"
        : "+f"(d[0]), "+f"(d[1]), "+f"(d[2]), "+f"(d[3])
        : "r"(a[0]), "r"(a[1]), "r"(a[2]), "r"(a[3]), "r"(b[0]), "r"(b[1]));
}
__device__ __forceinline__ void cpa16(uint32_t dst, const void* src) {
    asm volatile("cp.async.cg.shared.global [%0], [%1], 16;" :: "r"(dst), "l"(src));
}
__device__ __forceinline__ void cpa_commit() {
    asm volatile("cp.async.commit_group;" ::: "memory");
}
template <int NW>
__device__ __forceinline__ void cpa_wait() {
    asm volatile("cp.async.wait_group %0;" :: "n"(NW) : "memory");
}

// ================ pre-pass: fp32 -> fp16, multi-segment ================
struct SplitSeg { const float* src; __half* dst; int n; };
struct SplitArgs { SplitSeg seg[8]; };

__global__ __launch_bounds__(256) void split_multi(SplitArgs a) {
    const SplitSeg g = a.seg[blockIdx.y];
    int i = (blockIdx.x * 256 + threadIdx.x) * 8;
    if (i >= g.n) return;
    float v[8];
    *(float4*)&v[0] = *(const float4*)(g.src + i);
    *(float4*)&v[4] = *(const float4*)(g.src + i + 4);
    uint32_t hw[4];
#pragma unroll
    for (int j = 0; j < 4; j++) {
        __half2 ph{__float2half_rn(v[2 * j]), __float2half_rn(v[2 * j + 1])};
        hw[j] = *reinterpret_cast<uint32_t*>(&ph);
    }
    *(uint4*)(g.dst + i) = make_uint4(hw[0], hw[1], hw[2], hw[3]);
}

// ============ skinny HMMA lora GEMM: U = ALPHA * X @ [Wac;Wae[e]]^T ============
#define LSTG 12288
#define LB_OFF 8192

__global__ __launch_bounds__(128) void lora_gemm(
    const __half* __restrict__ X, const __half* __restrict__ Wac,
    const __half* __restrict__ Wae, const int* __restrict__ eids,
    __half* __restrict__ U, int K)
{
    extern __shared__ char smraw[];
    uint32_t sd0 = smem_u32(smraw);
    char* smem = smraw + (((sd0 + 1023u) & ~1023u) - sd0);
    const uint32_t Sb = smem_u32(smem);

    const int tid = threadIdx.x, wid = tid >> 5, lane = tid & 31;
    const int m0 = blockIdx.x * 64;
    const int e = eids[m0 >> 9];
    const int m_w = wid * 16;

    const int arow = lane & 15, ac8 = (lane >> 4) * 16;
    const int brow_base = ((lane >> 4) & 1) * 8 + (lane & 7);
    const int bk8 = ((lane >> 3) & 1) * 16;

    float acc[4][4];
#pragma unroll
    for (int i = 0; i < 4; i++)
#pragma unroll
        for (int q = 0; q < 4; q++) acc[i][q] = 0.f;

    const int KCH = K >> 6;
    const int srow = tid >> 1, shf = tid & 1;

    auto load_stage = [&](int ch, int s) {
        const uint32_t Ab = Sb + s * LSTG;
        const int kc = ch << 6;
        {
            const __half* sh = X + (size_t)(m0 + srow) * K + kc + shf * 32;
            const uint32_t ro = (uint32_t)srow * 128, xm = (uint32_t)(srow & 7) << 4;
#pragma unroll
            for (int j = 0; j < 4; j++)
                cpa16(Ab + ro + (((uint32_t)(shf * 64 + j * 16)) ^ xm), sh + j * 8);
        }
        if (tid < 64) {
            const int row = tid >> 1, bhf = tid & 1;
            const __half* sb = (row < 16)
                ? (Wac + (size_t)row * K + kc + bhf * 32)
                : (Wae + ((size_t)e * 16 + (row - 16)) * (size_t)K + kc + bhf * 32);
            const uint32_t ro = (uint32_t)row * 128, xm = (uint32_t)(row & 7) << 4;
#pragma unroll
            for (int j = 0; j < 4; j++)
                cpa16(Ab + LB_OFF + ro + (((uint32_t)(bhf * 64 + j * 16)) ^ xm), sb + j * 8);
        }
    };

    auto compute_stage = [&](int s) {
        const uint32_t Ab = Sb + s * LSTG;
#pragma unroll
        for (int ks = 0; ks < 4; ks++) {
            const int kb = ks * 32;
            uint32_t ah[4], bh[2][4];
            {
                int row = m_w + arow;
                ldsm_x4(ah, Ab + (uint32_t)row * 128 +
                            ((uint32_t)(kb + ac8) ^ ((uint32_t)(row & 7) << 4)));
            }
#pragma unroll
            for (int p = 0; p < 2; p++) {
                int row = p * 16 + brow_base;
                ldsm_x4(bh[p], Ab + LB_OFF + (uint32_t)row * 128 +
                               ((uint32_t)(kb + bk8) ^ ((uint32_t)(row & 7) << 4)));
            }
#pragma unroll
            for (int ni = 0; ni < 4; ni++)
                mma_f16(acc[ni], ah, &bh[ni >> 1][(ni & 1) * 2]);
        }
    };

    load_stage(0, 0);
    cpa_commit();
    for (int ch = 0; ch < KCH; ch++) {
        if (ch + 1 < KCH) {
            load_stage(ch + 1, (ch + 1) & 1);
            cpa_commit();
            cpa_wait<1>();
        } else {
            cpa_wait<0>();
        }
        __syncthreads();
        compute_stage(ch & 1);
        __syncthreads();
    }

    const int er = lane >> 2, ec = (lane & 3) * 2;
#pragma unroll
    for (int ni = 0; ni < 4; ni++) {
#pragma unroll
        for (int hrow = 0; hrow < 2; hrow++) {
            int gr = m0 + m_w + er + hrow * 8;
            int gc = ni * 8 + ec;
            __half2 v{__float2half_rn(ALPHA_F * acc[ni][hrow * 2]),
                      __float2half_rn(ALPHA_F * acc[ni][hrow * 2 + 1])};
            *reinterpret_cast<__half2*>(U + (size_t)gr * 32 + gc) = v;
        }
    }
}

// ===== single-product fp16 GEMM + fused LoRA: 4 warps @ 64x64, 3-stage =====
// CTA 128x128, BK=64, 128 threads, 2 CTAs/SM. Stage: A 16K | B 16K = 32KB x3.
#define GSTG 32768
#define GB_OFF 16384
#define GSMEM (3 * GSTG + 1024)

template <int MODE>  // 1: relu -> fp16 out; 0: fp32 out
__global__ __launch_bounds__(128, 2) void gemm_cp(
    const __half* __restrict__ A, const __half* __restrict__ B,
    const __half* __restrict__ U,
    const __half* __restrict__ Wbc, const __half* __restrict__ Wbe,
    const int* __restrict__ eids,
    float* __restrict__ outF, __half* __restrict__ outH, int N, int K)
{
    extern __shared__ char smraw[];
    uint32_t sd0 = smem_u32(smraw);
    char* smem = smraw + (((sd0 + 1023u) & ~1023u) - sd0);
    const uint32_t Sb = smem_u32(smem);

    const int tid = threadIdx.x, wid = tid >> 5, lane = tid & 31;
    const int m0 = blockIdx.y * 128, n0 = blockIdx.x * 128;
    const int e = eids[m0 >> 9];

    // 4 warps: 2M x 2N, each 64x64
    const int m_w = (wid >> 1) * 64, n_w = (wid & 1) * 64;
    const int arow = lane & 15, ac8 = (lane >> 4) * 16;
    const int brow_base = ((lane >> 4) & 1) * 8 + (lane & 7);
    const int bk8 = ((lane >> 3) & 1) * 16;

    float acc[4][8][4];
#pragma unroll
    for (int i = 0; i < 4; i++)
#pragma unroll
        for (int j = 0; j < 8; j++)
#pragma unroll
            for (int q = 0; q < 4; q++) acc[i][j][q] = 0.f;

    const int KCH = K >> 6, NCH = KCH + 1;

    // staging: 128 threads, thread = one row of A and one row of B (128B each)
    auto load_stage = [&](int ch, int s) {
        const uint32_t Ab = Sb + (uint32_t)s * GSTG;
        const int row = tid;
        const uint32_t ro = (uint32_t)row * 128, xm = (uint32_t)(row & 7) << 4;
        if (ch < KCH) {
            const int kc = ch << 6;
            const __half* sa = A + (size_t)(m0 + row) * K + kc;
            const __half* sb = B + (size_t)(n0 + row) * K + kc;
#pragma unroll
            for (int j = 0; j < 8; j++) {
                uint32_t d = ((uint32_t)(j * 16)) ^ xm;
                cpa16(Ab + ro + d, sa + j * 8);
                cpa16(Ab + GB_OFF + ro + d, sb + j * 8);
            }
        } else {
            // lora chunk: A = U[m,0:32]; B k 0:16 = Wbc, 16:32 = Wbe[e]
            const __half* su = U + (size_t)(m0 + row) * 32;
#pragma unroll
            for (int j = 0; j < 4; j++)
                cpa16(Ab + ro + (((uint32_t)(j * 16)) ^ xm), su + j * 8);
            const __half* sc = Wbc + (size_t)(n0 + row) * 16;
            const __half* se = Wbe + (size_t)e * N * 16 + (size_t)(n0 + row) * 16;
#pragma unroll
            for (int j = 0; j < 2; j++) {
                cpa16(Ab + GB_OFF + ro + (((uint32_t)(j * 16)) ^ xm), sc + j * 8);
                cpa16(Ab + GB_OFF + ro + (((uint32_t)(32 + j * 16)) ^ xm), se + j * 8);
            }
        }
    };

    auto compute_stage = [&](int s, int nks) {
        const uint32_t Ab = Sb + (uint32_t)s * GSTG;
#pragma unroll
        for (int ks = 0; ks < 4; ks++) {
            if (ks >= nks) break;
            const int kb = ks * 32;
            uint32_t ah[4][4], bh[4][4];
#pragma unroll
            for (int mi = 0; mi < 4; mi++) {
                int row = m_w + mi * 16 + arow;
                ldsm_x4(ah[mi], Ab + (uint32_t)row * 128 +
                                ((uint32_t)(kb + ac8) ^ ((uint32_t)(row & 7) << 4)));
            }
#pragma unroll
            for (int p = 0; p < 4; p++) {
                int row = n_w + p * 16 + brow_base;
                ldsm_x4(bh[p], Ab + GB_OFF + (uint32_t)row * 128 +
                               ((uint32_t)(kb + bk8) ^ ((uint32_t)(row & 7) << 4)));
            }
#pragma unroll
            for (int mi = 0; mi < 4; mi++)
#pragma unroll
                for (int ni = 0; ni < 8; ni++)
                    mma_f16(acc[mi][ni], ah[mi], &bh[ni >> 1][(ni & 1) * 2]);
        }
    };

    // ---- 3-stage pipeline, one sync per chunk ----
    load_stage(0, 0);
    cpa_commit();
    load_stage(1, 1);
    cpa_commit();
    int s3 = 0;
    for (int ch = 0; ch < NCH; ch++) {
        if (ch + 1 < NCH) cpa_wait<1>();
        else cpa_wait<0>();
        __syncthreads();
        compute_stage(s3, (ch < KCH) ? 4 : 2);
        if (ch + 2 < NCH) {
            int sn = s3 + 2;
            if (sn >= 3) sn -= 3;
            load_stage(ch + 2, sn);
            cpa_commit();
        }
        if (++s3 == 3) s3 = 0;
    }

    // ---- epilogue ----
    const int er = lane >> 2, ec = (lane & 3) * 2;
#pragma unroll
    for (int mi = 0; mi < 4; mi++) {
#pragma unroll
        for (int ni = 0; ni < 8; ni++) {
            float* d = acc[mi][ni];
            int gr0 = m0 + m_w + mi * 16 + er;
            int gc = n0 + n_w + ni * 8 + ec;
#pragma unroll
            for (int hrow = 0; hrow < 2; hrow++) {
                int gr = gr0 + hrow * 8;
                if (MODE == 1) {
                    float v0 = fmaxf(d[hrow * 2], 0.f), v1 = fmaxf(d[hrow * 2 + 1], 0.f);
                    __half2 ph{__float2half_rn(v0), __float2half_rn(v1)};
                    *reinterpret_cast<__half2*>(outH + (size_t)gr * N + gc) = ph;
                } else {
                    float2 v{d[hrow * 2], d[hrow * 2 + 1]};
                    *reinterpret_cast<float2*>(outF + (size_t)gr * N + gc) = v;
                }
            }
        }
    }
}

// =============================== launch ===============================
extern "C" void kernel_launch(void* const* d_in, const int* in_sizes, int n_in,
                              void* d_out, int out_size)
{
    (void)in_sizes; (void)n_in; (void)out_size;
    const float* x     = (const float*)d_in[0];
    const int*   eids  = (const int*)d_in[1];
    const float* wi    = (const float*)d_in[2];
    const float* wo    = (const float*)d_in[3];
    const float* cwi_a = (const float*)d_in[4];
    const float* cwi_b = (const float*)d_in[5];
    const float* cwo_a = (const float*)d_in[6];
    const float* cwo_b = (const float*)d_in[7];
    const float* ewi_a = (const float*)d_in[8];
    const float* ewi_b = (const float*)d_in[9];
    const float* ewo_a = (const float*)d_in[10];
    const float* ewo_b = (const float*)d_in[11];
    float* out = (float*)d_out;

    __half *hid, *xh, *wih, *woh, *U1, *U2;
    __half *wbc1, *wbe1, *wbc2, *wbe2, *wac1, *wae1, *wac2, *wae2;
    cudaGetSymbolAddress((void**)&hid, g_hid);
    cudaGetSymbolAddress((void**)&xh, g_x);
    cudaGetSymbolAddress((void**)&wih, g_wi);
    cudaGetSymbolAddress((void**)&woh, g_wo);
    cudaGetSymbolAddress((void**)&U1, g_U1);
    cudaGetSymbolAddress((void**)&U2, g_U2);
    cudaGetSymbolAddress((void**)&wbc1, g_wbc1);
    cudaGetSymbolAddress((void**)&wbe1, g_wbe1);
    cudaGetSymbolAddress((void**)&wbc2, g_wbc2);
    cudaGetSymbolAddress((void**)&wbe2, g_wbe2);
    cudaGetSymbolAddress((void**)&wac1, g_wac1);
    cudaGetSymbolAddress((void**)&wae1, g_wae1);
    cudaGetSymbolAddress((void**)&wac2, g_wac2);
    cudaGetSymbolAddress((void**)&wae2, g_wae2);

    cudaFuncSetAttribute(gemm_cp<1>, cudaFuncAttributeMaxDynamicSharedMemorySize, GSMEM);
    cudaFuncSetAttribute(gemm_cp<0>, cudaFuncAttributeMaxDynamicSharedMemorySize, GSMEM);
    const int LSMEM = 2 * LSTG + 1024;
    cudaFuncSetAttribute(lora_gemm, cudaFuncAttributeMaxDynamicSharedMemorySize, LSMEM);

    // ---- merged pre-splits: 2 launches ----
    {   // big: x, wi, wo
        SplitArgs a{};
        a.seg[0] = { x,  xh,  T_TOK * D_DIM };
        a.seg[1] = { wi, wih, F_DIM * D_DIM };
        a.seg[2] = { wo, woh, D_DIM * F_DIM };
        dim3 g((T_TOK * D_DIM) / 2048, 3);
        split_multi<<<g, 256>>>(a);
    }
    {   // small: all LoRA weights
        SplitArgs a{};
        a.seg[0] = { cwi_b, wbc1, F_DIM * 16 };
        a.seg[1] = { ewi_b, wbe1, E_EXP * F_DIM * 16 };
        a.seg[2] = { cwo_b, wbc2, D_DIM * 16 };
        a.seg[3] = { ewo_b, wbe2, E_EXP * D_DIM * 16 };
        a.seg[4] = { cwi_a, wac1, 16 * D_DIM };
        a.seg[5] = { ewi_a, wae1, E_EXP * 16 * D_DIM };
        a.seg[6] = { cwo_a, wac2, 16 * F_DIM };
        a.seg[7] = { ewo_a, wae2, E_EXP * 16 * F_DIM };
        dim3 g((E_EXP * F_DIM * 16) / 2048, 8);
        split_multi<<<g, 256>>>(a);
    }

    // stage 1
    lora_gemm<<<T_TOK / 64, 128, LSMEM>>>(xh, wac1, wae1, eids, U1, D_DIM);
    dim3 g1(F_DIM / 128, T_TOK / 128);
    gemm_cp<1><<<g1, 128, GSMEM>>>(xh, wih, U1, wbc1, wbe1, eids,
                                   nullptr, hid, F_DIM, D_DIM);

    // stage 2
    lora_gemm<<<T_TOK / 64, 128, LSMEM>>>(hid, wac2, wae2, eids, U2, F_DIM);
    dim3 g2(D_DIM / 128, T_TOK / 128);
    gemm_cp<0><<<g2, 128, GSMEM>>>(hid, woh, U2, wbc2, wbe2, eids,
                                   out, nullptr, D_DIM, F_DIM);
}

// round 13
// speedup vs baseline: 1.4074x; 1.4074x over previous
#include <cuda_runtime.h>
#include <cuda_fp16.h>
#include <cstdint>
#include <cstddef>

#define T_TOK 16384
#define D_DIM 1024
#define F_DIM 4096
#define E_EXP 8
#define ALPHA_F 2.0f

// ---- device scratch (allocation-free; all fp16 hi-only) ----
__device__ __half g_hid[(size_t)T_TOK * F_DIM];
__device__ __half g_x[(size_t)T_TOK * D_DIM];
__device__ __half g_wi[(size_t)F_DIM * D_DIM];
__device__ __half g_wo[(size_t)D_DIM * F_DIM];
__device__ __half g_U1[T_TOK * 32];
__device__ __half g_U2[T_TOK * 32];
__device__ __half g_wbc1[F_DIM * 16];
__device__ __half g_wbe1[E_EXP * F_DIM * 16];
__device__ __half g_wbc2[D_DIM * 16];
__device__ __half g_wbe2[E_EXP * D_DIM * 16];
__device__ __half g_wac1[16 * D_DIM];
__device__ __half g_wae1[E_EXP * 16 * D_DIM];
__device__ __half g_wac2[16 * F_DIM];
__device__ __half g_wae2[E_EXP * 16 * F_DIM];

// ---------------- helpers ----------------
__device__ __forceinline__ uint32_t smem_u32(const void* p) {
    uint32_t a;
    asm("{ .reg .u64 t; cvta.to.shared.u64 t, %1; cvt.u32.u64 %0, t; }" : "=r"(a) : "l"(p));
    return a;
}
__device__ __forceinline__ void ldsm_x4(uint32_t* r, uint32_t addr) {
    asm volatile("ldmatrix.sync.aligned.m8n8.x4.shared.b16 {%0,%1,%2,%3}, [%4];"
                 : "=r"(r[0]), "=r"(r[1]), "=r"(r[2]), "=r"(r[3]) : "r"(addr));
}
__device__ __forceinline__ void mma_f16(float* d, const uint32_t* a, const uint32_t* b) {
    asm volatile(
        "mma.sync.aligned.m16n8k16.row.col.f32.f16.f16.f32 "
        "{%0,%1,%2,%3},{%4,%5,%6,%7},{%8,%9},{%0,%1,%2,%3};"
        : "+f"(d[0]), "+f"(d[1]), "+f"(d[2]), "+f"(d[3])
        : "r"(a[0]), "r"(a[1]), "r"(a[2]), "r"(a[3]), "r"(b[0]), "r"(b[1]));
}
__device__ __forceinline__ void cpa16(uint32_t dst, const void* src) {
    asm volatile("cp.async.cg.shared.global [%0], [%1], 16;" :: "r"(dst), "l"(src));
}
__device__ __forceinline__ void cpa_commit() {
    asm volatile("cp.async.commit_group;" ::: "memory");
}
template <int NW>
__device__ __forceinline__ void cpa_wait() {
    asm volatile("cp.async.wait_group %0;" :: "n"(NW) : "memory");
}

// ================ pre-pass: fp32 -> fp16, multi-segment ================
struct SplitSeg { const float* src; __half* dst; int n; };
struct SplitArgs { SplitSeg seg[8]; };

__global__ __launch_bounds__(256) void split_multi(SplitArgs a) {
    const SplitSeg g = a.seg[blockIdx.y];
    int i = (blockIdx.x * 256 + threadIdx.x) * 8;
    if (i >= g.n) return;
    float v[8];
    *(float4*)&v[0] = *(const float4*)(g.src + i);
    *(float4*)&v[4] = *(const float4*)(g.src + i + 4);
    uint32_t hw[4];
#pragma unroll
    for (int j = 0; j < 4; j++) {
        __half2 ph{__float2half_rn(v[2 * j]), __float2half_rn(v[2 * j + 1])};
        hw[j] = *reinterpret_cast<uint32_t*>(&ph);
    }
    *(uint4*)(g.dst + i) = make_uint4(hw[0], hw[1], hw[2], hw[3]);
}

// ============ skinny HMMA lora GEMM: U = ALPHA * X @ [Wac;Wae[e]]^T ============
#define LSTG 12288
#define LB_OFF 8192

__global__ __launch_bounds__(128) void lora_gemm(
    const __half* __restrict__ X, const __half* __restrict__ Wac,
    const __half* __restrict__ Wae, const int* __restrict__ eids,
    __half* __restrict__ U, int K)
{
    extern __shared__ char smraw[];
    uint32_t sd0 = smem_u32(smraw);
    char* smem = smraw + (((sd0 + 1023u) & ~1023u) - sd0);
    const uint32_t Sb = smem_u32(smem);

    const int tid = threadIdx.x, wid = tid >> 5, lane = tid & 31;
    const int m0 = blockIdx.x * 64;
    const int e = eids[m0 >> 9];
    const int m_w = wid * 16;

    const int arow = lane & 15, ac8 = (lane >> 4) * 16;
    const int brow_base = ((lane >> 4) & 1) * 8 + (lane & 7);
    const int bk8 = ((lane >> 3) & 1) * 16;

    float acc[4][4];
#pragma unroll
    for (int i = 0; i < 4; i++)
#pragma unroll
        for (int q = 0; q < 4; q++) acc[i][q] = 0.f;

    const int KCH = K >> 6;
    const int srow = tid >> 1, shf = tid & 1;

    auto load_stage = [&](int ch, int s) {
        const uint32_t Ab = Sb + s * LSTG;
        const int kc = ch << 6;
        {
            const __half* sh = X + (size_t)(m0 + srow) * K + kc + shf * 32;
            const uint32_t ro = (uint32_t)srow * 128, xm = (uint32_t)(srow & 7) << 4;
#pragma unroll
            for (int j = 0; j < 4; j++)
                cpa16(Ab + ro + (((uint32_t)(shf * 64 + j * 16)) ^ xm), sh + j * 8);
        }
        if (tid < 64) {
            const int row = tid >> 1, bhf = tid & 1;
            const __half* sb = (row < 16)
                ? (Wac + (size_t)row * K + kc + bhf * 32)
                : (Wae + ((size_t)e * 16 + (row - 16)) * (size_t)K + kc + bhf * 32);
            const uint32_t ro = (uint32_t)row * 128, xm = (uint32_t)(row & 7) << 4;
#pragma unroll
            for (int j = 0; j < 4; j++)
                cpa16(Ab + LB_OFF + ro + (((uint32_t)(bhf * 64 + j * 16)) ^ xm), sb + j * 8);
        }
    };

    auto compute_stage = [&](int s) {
        const uint32_t Ab = Sb + s * LSTG;
#pragma unroll
        for (int ks = 0; ks < 4; ks++) {
            const int kb = ks * 32;
            uint32_t ah[4], bh[2][4];
            {
                int row = m_w + arow;
                ldsm_x4(ah, Ab + (uint32_t)row * 128 +
                            ((uint32_t)(kb + ac8) ^ ((uint32_t)(row & 7) << 4)));
            }
#pragma unroll
            for (int p = 0; p < 2; p++) {
                int row = p * 16 + brow_base;
                ldsm_x4(bh[p], Ab + LB_OFF + (uint32_t)row * 128 +
                               ((uint32_t)(kb + bk8) ^ ((uint32_t)(row & 7) << 4)));
            }
#pragma unroll
            for (int ni = 0; ni < 4; ni++)
                mma_f16(acc[ni], ah, &bh[ni >> 1][(ni & 1) * 2]);
        }
    };

    load_stage(0, 0);
    cpa_commit();
    for (int ch = 0; ch < KCH; ch++) {
        if (ch + 1 < KCH) {
            load_stage(ch + 1, (ch + 1) & 1);
            cpa_commit();
            cpa_wait<1>();
        } else {
            cpa_wait<0>();
        }
        __syncthreads();
        compute_stage(ch & 1);
        __syncthreads();
    }

    const int er = lane >> 2, ec = (lane & 3) * 2;
#pragma unroll
    for (int ni = 0; ni < 4; ni++) {
#pragma unroll
        for (int hrow = 0; hrow < 2; hrow++) {
            int gr = m0 + m_w + er + hrow * 8;
            int gc = ni * 8 + ec;
            __half2 v{__float2half_rn(ALPHA_F * acc[ni][hrow * 2]),
                      __float2half_rn(ALPHA_F * acc[ni][hrow * 2 + 1])};
            *reinterpret_cast<__half2*>(U + (size_t)gr * 32 + gc) = v;
        }
    }
}

// ===== single-product fp16 GEMM + fused LoRA: 8 warps @ 32x64, 3-stage =====
// CTA 128x128, BK=64, 256 threads, 2 CTAs/SM. Stage: A 16K | B 16K = 32KB x3.
#define GSTG 32768
#define GB_OFF 16384
#define GSMEM (3 * GSTG + 1024)

template <int MODE>  // 1: relu -> fp16 out; 0: fp32 out
__global__ __launch_bounds__(256, 2) void gemm_cp(
    const __half* __restrict__ A, const __half* __restrict__ B,
    const __half* __restrict__ U,
    const __half* __restrict__ Wbc, const __half* __restrict__ Wbe,
    const int* __restrict__ eids,
    float* __restrict__ outF, __half* __restrict__ outH, int N, int K)
{
    extern __shared__ char smraw[];
    uint32_t sd0 = smem_u32(smraw);
    char* smem = smraw + (((sd0 + 1023u) & ~1023u) - sd0);
    const uint32_t Sb = smem_u32(smem);

    const int tid = threadIdx.x, wid = tid >> 5, lane = tid & 31;
    const int m0 = blockIdx.y * 128, n0 = blockIdx.x * 128;
    const int e = eids[m0 >> 9];

    const int m_w = (wid >> 1) * 32, n_w = (wid & 1) * 64;
    const int arow = lane & 15, ac8 = (lane >> 4) * 16;
    const int brow_base = ((lane >> 4) & 1) * 8 + (lane & 7);
    const int bk8 = ((lane >> 3) & 1) * 16;

    float acc[2][8][4];
#pragma unroll
    for (int i = 0; i < 2; i++)
#pragma unroll
        for (int j = 0; j < 8; j++)
#pragma unroll
            for (int q = 0; q < 4; q++) acc[i][j][q] = 0.f;

    const int KCH = K >> 6, NCH = KCH + 1;
    const int srow = tid >> 1, shf = tid & 1;

    auto load_stage = [&](int ch, int s) {
        const uint32_t Ab = Sb + (uint32_t)s * GSTG;
        const uint32_t ro = (uint32_t)srow * 128, xm = (uint32_t)(srow & 7) << 4;
        if (ch < KCH) {
            const int kc = ch << 6;
            const __half* sa = A + (size_t)(m0 + srow) * K + kc + shf * 32;
            const __half* sb = B + (size_t)(n0 + srow) * K + kc + shf * 32;
#pragma unroll
            for (int j = 0; j < 4; j++) {
                uint32_t d = ((uint32_t)(shf * 64 + j * 16)) ^ xm;
                cpa16(Ab + ro + d, sa + j * 8);
                cpa16(Ab + GB_OFF + ro + d, sb + j * 8);
            }
        } else {
            const __half* su = U + (size_t)(m0 + srow) * 32 + shf * 16;
            const __half* sb = shf
                ? (Wbe + (size_t)e * N * 16 + (size_t)(n0 + srow) * 16)
                : (Wbc + (size_t)(n0 + srow) * 16);
#pragma unroll
            for (int j = 0; j < 2; j++) {
                uint32_t d = ((uint32_t)(shf * 32 + j * 16)) ^ xm;
                cpa16(Ab + ro + d, su + j * 8);
                cpa16(Ab + GB_OFF + ro + d, sb + j * 8);
            }
        }
    };

    auto compute_stage = [&](int s, int nks) {
        const uint32_t Ab = Sb + (uint32_t)s * GSTG;
#pragma unroll
        for (int ks = 0; ks < 4; ks++) {
            if (ks >= nks) break;
            const int kb = ks * 32;
            uint32_t ah[2][4], bh[4][4];
#pragma unroll
            for (int mi = 0; mi < 2; mi++) {
                int row = m_w + mi * 16 + arow;
                ldsm_x4(ah[mi], Ab + (uint32_t)row * 128 +
                                ((uint32_t)(kb + ac8) ^ ((uint32_t)(row & 7) << 4)));
            }
#pragma unroll
            for (int p = 0; p < 4; p++) {
                int row = n_w + p * 16 + brow_base;
                ldsm_x4(bh[p], Ab + GB_OFF + (uint32_t)row * 128 +
                               ((uint32_t)(kb + bk8) ^ ((uint32_t)(row & 7) << 4)));
            }
#pragma unroll
            for (int mi = 0; mi < 2; mi++)
#pragma unroll
                for (int ni = 0; ni < 8; ni++)
                    mma_f16(acc[mi][ni], ah[mi], &bh[ni >> 1][(ni & 1) * 2]);
        }
    };

    // ---- 3-stage pipeline: load ch+2 issued BEFORE compute(ch) ----
    load_stage(0, 0);
    cpa_commit();
    load_stage(1, 1);
    cpa_commit();
    int s3 = 0;
    for (int ch = 0; ch < NCH; ch++) {
        if (ch + 1 < NCH) cpa_wait<1>();
        else cpa_wait<0>();
        __syncthreads();
        if (ch + 2 < NCH) {
            // stage (s3+2)%3 held chunk ch-1, fully consumed before this barrier
            int sn = s3 + 2;
            if (sn >= 3) sn -= 3;
            load_stage(ch + 2, sn);
            cpa_commit();
        }
        compute_stage(s3, (ch < KCH) ? 4 : 2);
        if (++s3 == 3) s3 = 0;
    }

    // ---- epilogue ----
    const int er = lane >> 2, ec = (lane & 3) * 2;
#pragma unroll
    for (int mi = 0; mi < 2; mi++) {
#pragma unroll
        for (int ni = 0; ni < 8; ni++) {
            float* d = acc[mi][ni];
            int gr0 = m0 + m_w + mi * 16 + er;
            int gc = n0 + n_w + ni * 8 + ec;
#pragma unroll
            for (int hrow = 0; hrow < 2; hrow++) {
                int gr = gr0 + hrow * 8;
                if (MODE == 1) {
                    float v0 = fmaxf(d[hrow * 2], 0.f), v1 = fmaxf(d[hrow * 2 + 1], 0.f);
                    __half2 ph{__float2half_rn(v0), __float2half_rn(v1)};
                    *reinterpret_cast<__half2*>(outH + (size_t)gr * N + gc) = ph;
                } else {
                    float2 v{d[hrow * 2], d[hrow * 2 + 1]};
                    *reinterpret_cast<float2*>(outF + (size_t)gr * N + gc) = v;
                }
            }
        }
    }
}

// =============================== launch ===============================
extern "C" void kernel_launch(void* const* d_in, const int* in_sizes, int n_in,
                              void* d_out, int out_size)
{
    (void)in_sizes; (void)n_in; (void)out_size;
    const float* x     = (const float*)d_in[0];
    const int*   eids  = (const int*)d_in[1];
    const float* wi    = (const float*)d_in[2];
    const float* wo    = (const float*)d_in[3];
    const float* cwi_a = (const float*)d_in[4];
    const float* cwi_b = (const float*)d_in[5];
    const float* cwo_a = (const float*)d_in[6];
    const float* cwo_b = (const float*)d_in[7];
    const float* ewi_a = (const float*)d_in[8];
    const float* ewi_b = (const float*)d_in[9];
    const float* ewo_a = (const float*)d_in[10];
    const float* ewo_b = (const float*)d_in[11];
    float* out = (float*)d_out;

    __half *hid, *xh, *wih, *woh, *U1, *U2;
    __half *wbc1, *wbe1, *wbc2, *wbe2, *wac1, *wae1, *wac2, *wae2;
    cudaGetSymbolAddress((void**)&hid, g_hid);
    cudaGetSymbolAddress((void**)&xh, g_x);
    cudaGetSymbolAddress((void**)&wih, g_wi);
    cudaGetSymbolAddress((void**)&woh, g_wo);
    cudaGetSymbolAddress((void**)&U1, g_U1);
    cudaGetSymbolAddress((void**)&U2, g_U2);
    cudaGetSymbolAddress((void**)&wbc1, g_wbc1);
    cudaGetSymbolAddress((void**)&wbe1, g_wbe1);
    cudaGetSymbolAddress((void**)&wbc2, g_wbc2);
    cudaGetSymbolAddress((void**)&wbe2, g_wbe2);
    cudaGetSymbolAddress((void**)&wac1, g_wac1);
    cudaGetSymbolAddress((void**)&wae1, g_wae1);
    cudaGetSymbolAddress((void**)&wac2, g_wac2);
    cudaGetSymbolAddress((void**)&wae2, g_wae2);

    cudaFuncSetAttribute(gemm_cp<1>, cudaFuncAttributeMaxDynamicSharedMemorySize, GSMEM);
    cudaFuncSetAttribute(gemm_cp<0>, cudaFuncAttributeMaxDynamicSharedMemorySize, GSMEM);
    const int LSMEM = 2 * LSTG + 1024;
    cudaFuncSetAttribute(lora_gemm, cudaFuncAttributeMaxDynamicSharedMemorySize, LSMEM);

    // ---- merged pre-splits: 2 launches ----
    {
        SplitArgs a{};
        a.seg[0] = { x,  xh,  T_TOK * D_DIM };
        a.seg[1] = { wi, wih, F_DIM * D_DIM };
        a.seg[2] = { wo, woh, D_DIM * F_DIM };
        dim3 g((T_TOK * D_DIM) / 2048, 3);
        split_multi<<<g, 256>>>(a);
    }
    {
        SplitArgs a{};
        a.seg[0] = { cwi_b, wbc1, F_DIM * 16 };
        a.seg[1] = { ewi_b, wbe1, E_EXP * F_DIM * 16 };
        a.seg[2] = { cwo_b, wbc2, D_DIM * 16 };
        a.seg[3] = { ewo_b, wbe2, E_EXP * D_DIM * 16 };
        a.seg[4] = { cwi_a, wac1, 16 * D_DIM };
        a.seg[5] = { ewi_a, wae1, E_EXP * 16 * D_DIM };
        a.seg[6] = { cwo_a, wac2, 16 * F_DIM };
        a.seg[7] = { ewo_a, wae2, E_EXP * 16 * F_DIM };
        dim3 g((E_EXP * F_DIM * 16) / 2048, 8);
        split_multi<<<g, 256>>>(a);
    }

    // stage 1
    lora_gemm<<<T_TOK / 64, 128, LSMEM>>>(xh, wac1, wae1, eids, U1, D_DIM);
    dim3 g1(F_DIM / 128, T_TOK / 128);
    gemm_cp<1><<<g1, 256, GSMEM>>>(xh, wih, U1, wbc1, wbe1, eids,
                                   nullptr, hid, F_DIM, D_DIM);

    // stage 2
    lora_gemm<<<T_TOK / 64, 128, LSMEM>>>(hid, wac2, wae2, eids, U2, F_DIM);
    dim3 g2(D_DIM / 128, T_TOK / 128);
    gemm_cp<0><<<g2, 256, GSMEM>>>(hid, woh, U2, wbc2, wbe2, eids,
                                   out, nullptr, D_DIM, F_DIM);
}

// round 14
// speedup vs baseline: 1.4896x; 1.0584x over previous
#include <cuda_runtime.h>
#include <cuda_fp16.h>
#include <cstdint>
#include <cstddef>

#define T_TOK 16384
#define D_DIM 1024
#define F_DIM 4096
#define E_EXP 8
#define ALPHA_F 2.0f

// ---- device scratch (allocation-free; all fp16 hi-only) ----
__device__ __half g_hid[(size_t)T_TOK * F_DIM];
__device__ __half g_x[(size_t)T_TOK * D_DIM];
__device__ __half g_wi[(size_t)F_DIM * D_DIM];
__device__ __half g_wo[(size_t)D_DIM * F_DIM];
__device__ __half g_U1[T_TOK * 32];
__device__ __half g_U2[T_TOK * 32];
__device__ __half g_wbc1[F_DIM * 16];
__device__ __half g_wbe1[E_EXP * F_DIM * 16];
__device__ __half g_wbc2[D_DIM * 16];
__device__ __half g_wbe2[E_EXP * D_DIM * 16];
__device__ __half g_wac1[16 * D_DIM];
__device__ __half g_wae1[E_EXP * 16 * D_DIM];
__device__ __half g_wac2[16 * F_DIM];
__device__ __half g_wae2[E_EXP * 16 * F_DIM];

// ---------------- helpers ----------------
__device__ __forceinline__ uint32_t smem_u32(const void* p) {
    uint32_t a;
    asm("{ .reg .u64 t; cvta.to.shared.u64 t, %1; cvt.u32.u64 %0, t; }" : "=r"(a) : "l"(p));
    return a;
}
__device__ __forceinline__ void ldsm_x4(uint32_t* r, uint32_t addr) {
    asm volatile("ldmatrix.sync.aligned.m8n8.x4.shared.b16 {%0,%1,%2,%3}, [%4];"
                 : "=r"(r[0]), "=r"(r[1]), "=r"(r[2]), "=r"(r[3]) : "r"(addr));
}
__device__ __forceinline__ void mma_f16(float* d, const uint32_t* a, const uint32_t* b) {
    asm volatile(
        "mma.sync.aligned.m16n8k16.row.col.f32.f16.f16.f32 "
        "{%0,%1,%2,%3},{%4,%5,%6,%7},{%8,%9},{%0,%1,%2,%3};"
        : "+f"(d[0]), "+f"(d[1]), "+f"(d[2]), "+f"(d[3])
        : "r"(a[0]), "r"(a[1]), "r"(a[2]), "r"(a[3]), "r"(b[0]), "r"(b[1]));
}
__device__ __forceinline__ void cpa16(uint32_t dst, const void* src) {
    asm volatile("cp.async.cg.shared.global [%0], [%1], 16;" :: "r"(dst), "l"(src));
}
__device__ __forceinline__ void cpa_commit() {
    asm volatile("cp.async.commit_group;" ::: "memory");
}
template <int NW>
__device__ __forceinline__ void cpa_wait() {
    asm volatile("cp.async.wait_group %0;" :: "n"(NW) : "memory");
}

// ================ pre-pass: fp32 -> fp16, multi-segment ================
struct SplitSeg { const float* src; __half* dst; int n; };
struct SplitArgs { SplitSeg seg[8]; };

__global__ __launch_bounds__(256) void split_multi(SplitArgs a) {
    const SplitSeg g = a.seg[blockIdx.y];
    int i = (blockIdx.x * 256 + threadIdx.x) * 8;
    if (i >= g.n) return;
    float v[8];
    *(float4*)&v[0] = *(const float4*)(g.src + i);
    *(float4*)&v[4] = *(const float4*)(g.src + i + 4);
    uint32_t hw[4];
#pragma unroll
    for (int j = 0; j < 4; j++) {
        __half2 ph{__float2half_rn(v[2 * j]), __float2half_rn(v[2 * j + 1])};
        hw[j] = *reinterpret_cast<uint32_t*>(&ph);
    }
    *(uint4*)(g.dst + i) = make_uint4(hw[0], hw[1], hw[2], hw[3]);
}

// ============ skinny HMMA lora GEMM: U = ALPHA * X @ [Wac;Wae[e]]^T ============
#define LSTG 12288
#define LB_OFF 8192

__global__ __launch_bounds__(128) void lora_gemm(
    const __half* __restrict__ X, const __half* __restrict__ Wac,
    const __half* __restrict__ Wae, const int* __restrict__ eids,
    __half* __restrict__ U, int K)
{
    extern __shared__ char smraw[];
    uint32_t sd0 = smem_u32(smraw);
    char* smem = smraw + (((sd0 + 1023u) & ~1023u) - sd0);
    const uint32_t Sb = smem_u32(smem);

    const int tid = threadIdx.x, wid = tid >> 5, lane = tid & 31;
    const int m0 = blockIdx.x * 64;
    const int e = eids[m0 >> 9];
    const int m_w = wid * 16;

    const int arow = lane & 15, ac8 = (lane >> 4) * 16;
    const int brow_base = ((lane >> 4) & 1) * 8 + (lane & 7);
    const int bk8 = ((lane >> 3) & 1) * 16;

    float acc[4][4];
#pragma unroll
    for (int i = 0; i < 4; i++)
#pragma unroll
        for (int q = 0; q < 4; q++) acc[i][q] = 0.f;

    const int KCH = K >> 6;
    const int srow = tid >> 1, shf = tid & 1;

    auto load_stage = [&](int ch, int s) {
        const uint32_t Ab = Sb + s * LSTG;
        const int kc = ch << 6;
        {
            const __half* sh = X + (size_t)(m0 + srow) * K + kc + shf * 32;
            const uint32_t ro = (uint32_t)srow * 128, xm = (uint32_t)(srow & 7) << 4;
#pragma unroll
            for (int j = 0; j < 4; j++)
                cpa16(Ab + ro + (((uint32_t)(shf * 64 + j * 16)) ^ xm), sh + j * 8);
        }
        if (tid < 64) {
            const int row = tid >> 1, bhf = tid & 1;
            const __half* sb = (row < 16)
                ? (Wac + (size_t)row * K + kc + bhf * 32)
                : (Wae + ((size_t)e * 16 + (row - 16)) * (size_t)K + kc + bhf * 32);
            const uint32_t ro = (uint32_t)row * 128, xm = (uint32_t)(row & 7) << 4;
#pragma unroll
            for (int j = 0; j < 4; j++)
                cpa16(Ab + LB_OFF + ro + (((uint32_t)(bhf * 64 + j * 16)) ^ xm), sb + j * 8);
        }
    };

    auto compute_stage = [&](int s) {
        const uint32_t Ab = Sb + s * LSTG;
#pragma unroll
        for (int ks = 0; ks < 4; ks++) {
            const int kb = ks * 32;
            uint32_t ah[4], bh[2][4];
            {
                int row = m_w + arow;
                ldsm_x4(ah, Ab + (uint32_t)row * 128 +
                            ((uint32_t)(kb + ac8) ^ ((uint32_t)(row & 7) << 4)));
            }
#pragma unroll
            for (int p = 0; p < 2; p++) {
                int row = p * 16 + brow_base;
                ldsm_x4(bh[p], Ab + LB_OFF + (uint32_t)row * 128 +
                               ((uint32_t)(kb + bk8) ^ ((uint32_t)(row & 7) << 4)));
            }
#pragma unroll
            for (int ni = 0; ni < 4; ni++)
                mma_f16(acc[ni], ah, &bh[ni >> 1][(ni & 1) * 2]);
        }
    };

    load_stage(0, 0);
    cpa_commit();
    for (int ch = 0; ch < KCH; ch++) {
        if (ch + 1 < KCH) {
            load_stage(ch + 1, (ch + 1) & 1);
            cpa_commit();
            cpa_wait<1>();
        } else {
            cpa_wait<0>();
        }
        __syncthreads();
        compute_stage(ch & 1);
        __syncthreads();
    }

    const int er = lane >> 2, ec = (lane & 3) * 2;
#pragma unroll
    for (int ni = 0; ni < 4; ni++) {
#pragma unroll
        for (int hrow = 0; hrow < 2; hrow++) {
            int gr = m0 + m_w + er + hrow * 8;
            int gc = ni * 8 + ec;
            __half2 v{__float2half_rn(ALPHA_F * acc[ni][hrow * 2]),
                      __float2half_rn(ALPHA_F * acc[ni][hrow * 2 + 1])};
            *reinterpret_cast<__half2*>(U + (size_t)gr * 32 + gc) = v;
        }
    }
}

// ===== single-product fp16 GEMM + fused LoRA: 8 warps @ 32x64, 3-stage =====
// CTA 128x128, BK=64, 256 threads, 2 CTAs/SM. Stage: A 16K | B 16K = 32KB x3.
// Loop schedule: R11-proven (wait -> sync -> compute -> load ch+2).
#define GSTG 32768
#define GB_OFF 16384
#define GSMEM (3 * GSTG + 1024)

template <int MODE>  // 1: relu -> fp16 out; 0: fp32 out
__global__ __launch_bounds__(256, 2) void gemm_cp(
    const __half* __restrict__ A, const __half* __restrict__ B,
    const __half* __restrict__ U,
    const __half* __restrict__ Wbc, const __half* __restrict__ Wbe,
    const int* __restrict__ eids,
    float* __restrict__ outF, __half* __restrict__ outH, int N, int K)
{
    extern __shared__ char smraw[];
    uint32_t sd0 = smem_u32(smraw);
    char* smem = smraw + (((sd0 + 1023u) & ~1023u) - sd0);
    const uint32_t Sb = smem_u32(smem);

    const int tid = threadIdx.x, wid = tid >> 5, lane = tid & 31;
    const int m0 = blockIdx.y * 128, n0 = blockIdx.x * 128;
    const int e = eids[m0 >> 9];

    const int m_w = (wid >> 1) * 32, n_w = (wid & 1) * 64;
    const int arow = lane & 15, ac8 = (lane >> 4) * 16;
    const int brow_base = ((lane >> 4) & 1) * 8 + (lane & 7);
    const int bk8 = ((lane >> 3) & 1) * 16;

    float acc[2][8][4];
#pragma unroll
    for (int i = 0; i < 2; i++)
#pragma unroll
        for (int j = 0; j < 8; j++)
#pragma unroll
            for (int q = 0; q < 4; q++) acc[i][j][q] = 0.f;

    const int KCH = K >> 6, NCH = KCH + 1;
    const int srow = tid >> 1, shf = tid & 1;

    auto load_stage = [&](int ch, int s) {
        const uint32_t Ab = Sb + (uint32_t)s * GSTG;
        const uint32_t ro = (uint32_t)srow * 128, xm = (uint32_t)(srow & 7) << 4;
        if (ch < KCH) {
            const int kc = ch << 6;
            const __half* sa = A + (size_t)(m0 + srow) * K + kc + shf * 32;
            const __half* sb = B + (size_t)(n0 + srow) * K + kc + shf * 32;
#pragma unroll
            for (int j = 0; j < 4; j++) {
                uint32_t d = ((uint32_t)(shf * 64 + j * 16)) ^ xm;
                cpa16(Ab + ro + d, sa + j * 8);
                cpa16(Ab + GB_OFF + ro + d, sb + j * 8);
            }
        } else {
            const __half* su = U + (size_t)(m0 + srow) * 32 + shf * 16;
            const __half* sb = shf
                ? (Wbe + (size_t)e * N * 16 + (size_t)(n0 + srow) * 16)
                : (Wbc + (size_t)(n0 + srow) * 16);
#pragma unroll
            for (int j = 0; j < 2; j++) {
                uint32_t d = ((uint32_t)(shf * 32 + j * 16)) ^ xm;
                cpa16(Ab + ro + d, su + j * 8);
                cpa16(Ab + GB_OFF + ro + d, sb + j * 8);
            }
        }
    };

    auto compute_stage = [&](int s, int nks) {
        const uint32_t Ab = Sb + (uint32_t)s * GSTG;
#pragma unroll
        for (int ks = 0; ks < 4; ks++) {
            if (ks >= nks) break;
            const int kb = ks * 32;
            uint32_t ah[2][4], bh[4][4];
#pragma unroll
            for (int mi = 0; mi < 2; mi++) {
                int row = m_w + mi * 16 + arow;
                ldsm_x4(ah[mi], Ab + (uint32_t)row * 128 +
                                ((uint32_t)(kb + ac8) ^ ((uint32_t)(row & 7) << 4)));
            }
#pragma unroll
            for (int p = 0; p < 4; p++) {
                int row = n_w + p * 16 + brow_base;
                ldsm_x4(bh[p], Ab + GB_OFF + (uint32_t)row * 128 +
                               ((uint32_t)(kb + bk8) ^ ((uint32_t)(row & 7) << 4)));
            }
#pragma unroll
            for (int mi = 0; mi < 2; mi++)
#pragma unroll
                for (int ni = 0; ni < 8; ni++)
                    mma_f16(acc[mi][ni], ah[mi], &bh[ni >> 1][(ni & 1) * 2]);
        }
    };

    // ---- 3-stage pipeline, R11 schedule: compute first, then load ch+2 ----
    load_stage(0, 0);
    cpa_commit();
    load_stage(1, 1);
    cpa_commit();
    int s3 = 0;
    for (int ch = 0; ch < NCH; ch++) {
        if (ch + 1 < NCH) cpa_wait<1>();
        else cpa_wait<0>();
        __syncthreads();
        compute_stage(s3, (ch < KCH) ? 4 : 2);
        if (ch + 2 < NCH) {
            int sn = s3 + 2;
            if (sn >= 3) sn -= 3;
            load_stage(ch + 2, sn);
            cpa_commit();
        }
        if (++s3 == 3) s3 = 0;
    }

    // ---- epilogue ----
    const int er = lane >> 2, ec = (lane & 3) * 2;
#pragma unroll
    for (int mi = 0; mi < 2; mi++) {
#pragma unroll
        for (int ni = 0; ni < 8; ni++) {
            float* d = acc[mi][ni];
            int gr0 = m0 + m_w + mi * 16 + er;
            int gc = n0 + n_w + ni * 8 + ec;
#pragma unroll
            for (int hrow = 0; hrow < 2; hrow++) {
                int gr = gr0 + hrow * 8;
                if (MODE == 1) {
                    float v0 = fmaxf(d[hrow * 2], 0.f), v1 = fmaxf(d[hrow * 2 + 1], 0.f);
                    __half2 ph{__float2half_rn(v0), __float2half_rn(v1)};
                    *reinterpret_cast<__half2*>(outH + (size_t)gr * N + gc) = ph;
                } else {
                    float2 v{d[hrow * 2], d[hrow * 2 + 1]};
                    *reinterpret_cast<float2*>(outF + (size_t)gr * N + gc) = v;
                }
            }
        }
    }
}

// =============================== launch ===============================
extern "C" void kernel_launch(void* const* d_in, const int* in_sizes, int n_in,
                              void* d_out, int out_size)
{
    (void)in_sizes; (void)n_in; (void)out_size;
    const float* x     = (const float*)d_in[0];
    const int*   eids  = (const int*)d_in[1];
    const float* wi    = (const float*)d_in[2];
    const float* wo    = (const float*)d_in[3];
    const float* cwi_a = (const float*)d_in[4];
    const float* cwi_b = (const float*)d_in[5];
    const float* cwo_a = (const float*)d_in[6];
    const float* cwo_b = (const float*)d_in[7];
    const float* ewi_a = (const float*)d_in[8];
    const float* ewi_b = (const float*)d_in[9];
    const float* ewo_a = (const float*)d_in[10];
    const float* ewo_b = (const float*)d_in[11];
    float* out = (float*)d_out;

    __half *hid, *xh, *wih, *woh, *U1, *U2;
    __half *wbc1, *wbe1, *wbc2, *wbe2, *wac1, *wae1, *wac2, *wae2;
    cudaGetSymbolAddress((void**)&hid, g_hid);
    cudaGetSymbolAddress((void**)&xh, g_x);
    cudaGetSymbolAddress((void**)&wih, g_wi);
    cudaGetSymbolAddress((void**)&woh, g_wo);
    cudaGetSymbolAddress((void**)&U1, g_U1);
    cudaGetSymbolAddress((void**)&U2, g_U2);
    cudaGetSymbolAddress((void**)&wbc1, g_wbc1);
    cudaGetSymbolAddress((void**)&wbe1, g_wbe1);
    cudaGetSymbolAddress((void**)&wbc2, g_wbc2);
    cudaGetSymbolAddress((void**)&wbe2, g_wbe2);
    cudaGetSymbolAddress((void**)&wac1, g_wac1);
    cudaGetSymbolAddress((void**)&wae1, g_wae1);
    cudaGetSymbolAddress((void**)&wac2, g_wac2);
    cudaGetSymbolAddress((void**)&wae2, g_wae2);

    cudaFuncSetAttribute(gemm_cp<1>, cudaFuncAttributeMaxDynamicSharedMemorySize, GSMEM);
    cudaFuncSetAttribute(gemm_cp<0>, cudaFuncAttributeMaxDynamicSharedMemorySize, GSMEM);
    const int LSMEM = 2 * LSTG + 1024;
    cudaFuncSetAttribute(lora_gemm, cudaFuncAttributeMaxDynamicSharedMemorySize, LSMEM);

    // ---- merged pre-splits: 2 launches ----
    {
        SplitArgs a{};
        a.seg[0] = { x,  xh,  T_TOK * D_DIM };
        a.seg[1] = { wi, wih, F_DIM * D_DIM };
        a.seg[2] = { wo, woh, D_DIM * F_DIM };
        dim3 g((T_TOK * D_DIM) / 2048, 3);
        split_multi<<<g, 256>>>(a);
    }
    {
        SplitArgs a{};
        a.seg[0] = { cwi_b, wbc1, F_DIM * 16 };
        a.seg[1] = { ewi_b, wbe1, E_EXP * F_DIM * 16 };
        a.seg[2] = { cwo_b, wbc2, D_DIM * 16 };
        a.seg[3] = { ewo_b, wbe2, E_EXP * D_DIM * 16 };
        a.seg[4] = { cwi_a, wac1, 16 * D_DIM };
        a.seg[5] = { ewi_a, wae1, E_EXP * 16 * D_DIM };
        a.seg[6] = { cwo_a, wac2, 16 * F_DIM };
        a.seg[7] = { ewo_a, wae2, E_EXP * 16 * F_DIM };
        dim3 g((E_EXP * F_DIM * 16) / 2048, 8);
        split_multi<<<g, 256>>>(a);
    }

    // stage 1
    lora_gemm<<<T_TOK / 64, 128, LSMEM>>>(xh, wac1, wae1, eids, U1, D_DIM);
    dim3 g1(F_DIM / 128, T_TOK / 128);
    gemm_cp<1><<<g1, 256, GSMEM>>>(xh, wih, U1, wbc1, wbe1, eids,
                                   nullptr, hid, F_DIM, D_DIM);

    // stage 2
    lora_gemm<<<T_TOK / 64, 128, LSMEM>>>(hid, wac2, wae2, eids, U2, F_DIM);
    dim3 g2(D_DIM / 128, T_TOK / 128);
    gemm_cp<0><<<g2, 256, GSMEM>>>(hid, woh, U2, wbc2, wbe2, eids,
                                   out, nullptr, D_DIM, F_DIM);
}